// round 1
// baseline (speedup 1.0000x reference)
#include <cuda_runtime.h>
#include <cstdint>

#define BATCH   4096
#define SEQ     32
#define DIM     256
#define VOCAB   50257
#define NALIVE  100

// Scratch (no allocations allowed): compacted nonzero activations per row.
__device__ float g_val[BATCH * NALIVE];
__device__ int   g_idx[BATCH * NALIVE];
__device__ int   g_cnt[BATCH];

__device__ __forceinline__ float warp_sum(float v) {
    #pragma unroll
    for (int off = 16; off > 0; off >>= 1)
        v += __shfl_xor_sync(0xFFFFFFFFu, v, off);
    return v;
}
__device__ __forceinline__ float warp_max(float v) {
    #pragma unroll
    for (int off = 16; off > 0; off >>= 1)
        v = fmaxf(v, __shfl_xor_sync(0xFFFFFFFFu, v, off));
    return v;
}

// One block per batch row: embed gather + attention pooling + RBF gate + compaction.
__global__ __launch_bounds__(256)
void ctx_act_kernel(const int*   __restrict__ tok,
                    const float* __restrict__ te,
                    const float* __restrict__ pe,
                    const float* __restrict__ q,
                    const float* __restrict__ pos) {
    __shared__ float s_emb[SEQ][DIM];     // 32 KB
    __shared__ float s_q[DIM];
    __shared__ float s_ctx[DIM];
    __shared__ float s_score[SEQ];
    __shared__ float s_w[SEQ];
    __shared__ float s_act[NALIVE];
    __shared__ int   s_tok[SEQ];

    const int b    = blockIdx.x;
    const int tid  = threadIdx.x;          // 0..255
    const int lane = tid & 31;
    const int wid  = tid >> 5;             // 0..7

    s_q[tid] = q[tid];
    if (tid < SEQ) s_tok[tid] = tok[b * SEQ + tid];
    __syncthreads();

    // Phase A: embeds[s][d] = te[tok[s]][d] + pe[s][d]  (coalesced 1KB rows)
    #pragma unroll 4
    for (int s = 0; s < SEQ; s++) {
        s_emb[s][tid] = te[(size_t)s_tok[s] * DIM + tid] + pe[s * DIM + tid];
    }
    __syncthreads();

    // Phase B: attention scores (warp w handles s = w, w+8, w+16, w+24)
    #pragma unroll
    for (int s = wid; s < SEQ; s += 8) {
        float p = 0.f;
        #pragma unroll
        for (int i = 0; i < 8; i++) {
            int d = lane + 32 * i;
            p = fmaf(s_emb[s][d], s_q[d], p);
        }
        p = warp_sum(p);
        if (lane == 0) s_score[s] = p * (1.0f / 16.0f);   // / sqrt(256)
    }
    __syncthreads();

    // Phase C: softmax over S=32 (warp 0, one score per lane)
    if (wid == 0) {
        float sc = s_score[lane];
        float m  = warp_max(sc);
        float e  = expf(sc - m);
        float s  = warp_sum(e);
        s_w[lane] = e / s;
    }
    __syncthreads();

    // Phase D: context[d] = sum_s w[s] * embeds[s][d]
    {
        float c = 0.f;
        #pragma unroll
        for (int s = 0; s < SEQ; s++) c = fmaf(s_w[s], s_emb[s][tid], c);
        s_ctx[tid] = c;
    }
    __syncthreads();

    // Phase E: RBF distances to 100 positions (warp w handles j = w, w+8, ...)
    for (int j = wid; j < NALIVE; j += 8) {
        float p = 0.f;
        #pragma unroll
        for (int i = 0; i < 8; i++) {
            int d = lane + 32 * i;
            float df = s_ctx[d] - pos[j * DIM + d];
            p = fmaf(df, df, p);
        }
        p = warp_sum(p);
        if (lane == 0) s_act[j] = expf(-2.0f * p);   // exp(-d2 / (2*0.5^2))
    }
    __syncthreads();

    // Phase F: normalize + compact nonzeros (warp 0)
    if (wid == 0) {
        float sum = 0.f;
        for (int j = lane; j < NALIVE; j += 32) sum += s_act[j];
        sum = warp_sum(sum);
        const float denom = sum + 1e-8f;

        int cnt = 0;
        #pragma unroll
        for (int base = 0; base < NALIVE; base += 32) {
            int j = base + lane;
            float a = 0.f;
            bool nz = false;
            if (j < NALIVE) {
                a  = s_act[j] / denom;
                nz = (a != 0.0f);
            }
            unsigned m = __ballot_sync(0xFFFFFFFFu, nz);
            int pre = __popc(m & ((1u << lane) - 1u));
            if (nz) {
                g_val[b * NALIVE + cnt + pre] = a;
                g_idx[b * NALIVE + cnt + pre] = j;
            }
            cnt += __popc(m);
        }
        if (lane == 0) g_cnt[b] = cnt;
    }
}

// logits[b, v] = sum_k val[k] * W[idx[k], v]; fast zero path when row is all-zero.
#define VTILE 2048
__global__ __launch_bounds__(256)
void logits_kernel(const float* __restrict__ W, float* __restrict__ out) {
    const int b   = blockIdx.y;
    const int v0  = blockIdx.x * VTILE;
    const int tid = threadIdx.x;
    const int vend = min(v0 + VTILE, VOCAB);
    float* __restrict__ orow = out + (size_t)b * VOCAB;

    const int cnt = g_cnt[b];
    if (cnt == 0) {
        // Pure streaming zero-fill (the overwhelmingly common case).
        for (int v = v0 + tid; v < vend; v += 256)
            __stcs(orow + v, 0.0f);
        return;
    }

    __shared__ float s_val[NALIVE];
    __shared__ int   s_idx[NALIVE];
    if (tid < cnt) {
        s_val[tid] = g_val[b * NALIVE + tid];
        s_idx[tid] = g_idx[b * NALIVE + tid];
    }
    __syncthreads();

    for (int v = v0 + tid; v < vend; v += 256) {
        float acc = 0.f;
        for (int k = 0; k < cnt; k++)
            acc = fmaf(s_val[k], W[(size_t)s_idx[k] * VOCAB + v], acc);
        __stcs(orow + v, acc);
    }
}

extern "C" void kernel_launch(void* const* d_in, const int* in_sizes, int n_in,
                              void* d_out, int out_size) {
    const int*   tok = (const int*)  d_in[0];   // [B, S]
    const float* te  = (const float*)d_in[1];   // [V, D]
    const float* pe  = (const float*)d_in[2];   // [S, D]
    const float* q   = (const float*)d_in[3];   // [D]
    const float* pos = (const float*)d_in[4];   // [N, D]
    const float* W   = (const float*)d_in[5];   // [N, V]
    float* out = (float*)d_out;                 // [B, V]

    ctx_act_kernel<<<BATCH, 256>>>(tok, te, pe, q, pos);

    dim3 grid((VOCAB + VTILE - 1) / VTILE, BATCH);
    logits_kernel<<<grid, 256>>>(W, out);
}

// round 2
// speedup vs baseline: 1.0018x; 1.0018x over previous
#include <cuda_runtime.h>
#include <cstdint>

#define BATCH   4096
#define SEQ     32
#define DIM     256
#define VOCAB   50257
#define NALIVE  100

// Scratch (no allocations allowed): compacted nonzero activations per row.
__device__ float g_val[BATCH * NALIVE];
__device__ int   g_idx[BATCH * NALIVE];
__device__ int   g_cnt[BATCH];

__device__ __forceinline__ float warp_sum(float v) {
    #pragma unroll
    for (int off = 16; off > 0; off >>= 1)
        v += __shfl_xor_sync(0xFFFFFFFFu, v, off);
    return v;
}
__device__ __forceinline__ float warp_max(float v) {
    #pragma unroll
    for (int off = 16; off > 0; off >>= 1)
        v = fmaxf(v, __shfl_xor_sync(0xFFFFFFFFu, v, off));
    return v;
}

// One block per batch row: embed gather + attention pooling + RBF gate + compaction.
__global__ __launch_bounds__(256)
void ctx_act_kernel(const int*   __restrict__ tok,
                    const float* __restrict__ te,
                    const float* __restrict__ pe,
                    const float* __restrict__ q,
                    const float* __restrict__ pos) {
    __shared__ float s_emb[SEQ][DIM];     // 32 KB
    __shared__ float s_q[DIM];
    __shared__ float s_ctx[DIM];
    __shared__ float s_score[SEQ];
    __shared__ float s_w[SEQ];
    __shared__ float s_act[NALIVE];
    __shared__ int   s_tok[SEQ];

    const int b    = blockIdx.x;
    const int tid  = threadIdx.x;          // 0..255
    const int lane = tid & 31;
    const int wid  = tid >> 5;             // 0..7

    s_q[tid] = q[tid];
    if (tid < SEQ) s_tok[tid] = tok[b * SEQ + tid];
    __syncthreads();

    // Phase A: embeds[s][d] = te[tok[s]][d] + pe[s][d]  (coalesced 1KB rows)
    #pragma unroll 4
    for (int s = 0; s < SEQ; s++) {
        s_emb[s][tid] = te[(size_t)s_tok[s] * DIM + tid] + pe[s * DIM + tid];
    }
    __syncthreads();

    // Phase B: attention scores (warp w handles s = w, w+8, w+16, w+24)
    #pragma unroll
    for (int s = wid; s < SEQ; s += 8) {
        float p = 0.f;
        #pragma unroll
        for (int i = 0; i < 8; i++) {
            int d = lane + 32 * i;
            p = fmaf(s_emb[s][d], s_q[d], p);
        }
        p = warp_sum(p);
        if (lane == 0) s_score[s] = p * (1.0f / 16.0f);   // / sqrt(256)
    }
    __syncthreads();

    // Phase C: softmax over S=32 (warp 0, one score per lane)
    if (wid == 0) {
        float sc = s_score[lane];
        float m  = warp_max(sc);
        float e  = expf(sc - m);
        float s  = warp_sum(e);
        s_w[lane] = e / s;
    }
    __syncthreads();

    // Phase D: context[d] = sum_s w[s] * embeds[s][d]
    {
        float c = 0.f;
        #pragma unroll
        for (int s = 0; s < SEQ; s++) c = fmaf(s_w[s], s_emb[s][tid], c);
        s_ctx[tid] = c;
    }
    __syncthreads();

    // Phase E: RBF distances to 100 positions (warp w handles j = w, w+8, ...)
    for (int j = wid; j < NALIVE; j += 8) {
        float p = 0.f;
        #pragma unroll
        for (int i = 0; i < 8; i++) {
            int d = lane + 32 * i;
            float df = s_ctx[d] - pos[j * DIM + d];
            p = fmaf(df, df, p);
        }
        p = warp_sum(p);
        if (lane == 0) s_act[j] = expf(-2.0f * p);   // exp(-d2 / (2*0.5^2))
    }
    __syncthreads();

    // Phase F: normalize + compact nonzeros (warp 0)
    if (wid == 0) {
        float sum = 0.f;
        for (int j = lane; j < NALIVE; j += 32) sum += s_act[j];
        sum = warp_sum(sum);
        const float denom = sum + 1e-8f;

        int cnt = 0;
        #pragma unroll
        for (int base = 0; base < NALIVE; base += 32) {
            int j = base + lane;
            float a = 0.f;
            bool nz = false;
            if (j < NALIVE) {
                a  = s_act[j] / denom;
                nz = (a != 0.0f);
            }
            unsigned m = __ballot_sync(0xFFFFFFFFu, nz);
            int pre = __popc(m & ((1u << lane) - 1u));
            if (nz) {
                g_val[b * NALIVE + cnt + pre] = a;
                g_idx[b * NALIVE + cnt + pre] = j;
            }
            cnt += __popc(m);
        }
        if (lane == 0) g_cnt[b] = cnt;
    }
}

// logits[b, v] = sum_k val[k] * W[idx[k], v]; fast zero path when row is all-zero.
#define VTILE 2048
__global__ __launch_bounds__(256)
void logits_kernel(const float* __restrict__ W, float* __restrict__ out) {
    const int b   = blockIdx.y;
    const int v0  = blockIdx.x * VTILE;
    const int tid = threadIdx.x;
    const int vend = min(v0 + VTILE, VOCAB);
    float* __restrict__ orow = out + (size_t)b * VOCAB;

    const int cnt = g_cnt[b];
    if (cnt == 0) {
        // Pure streaming zero-fill (the overwhelmingly common case).
        for (int v = v0 + tid; v < vend; v += 256)
            __stcs(orow + v, 0.0f);
        return;
    }

    __shared__ float s_val[NALIVE];
    __shared__ int   s_idx[NALIVE];
    if (tid < cnt) {
        s_val[tid] = g_val[b * NALIVE + tid];
        s_idx[tid] = g_idx[b * NALIVE + tid];
    }
    __syncthreads();

    for (int v = v0 + tid; v < vend; v += 256) {
        float acc = 0.f;
        for (int k = 0; k < cnt; k++)
            acc = fmaf(s_val[k], W[(size_t)s_idx[k] * VOCAB + v], acc);
        __stcs(orow + v, acc);
    }
}

extern "C" void kernel_launch(void* const* d_in, const int* in_sizes, int n_in,
                              void* d_out, int out_size) {
    const int*   tok = (const int*)  d_in[0];   // [B, S]
    const float* te  = (const float*)d_in[1];   // [V, D]
    const float* pe  = (const float*)d_in[2];   // [S, D]
    const float* q   = (const float*)d_in[3];   // [D]
    const float* pos = (const float*)d_in[4];   // [N, D]
    const float* W   = (const float*)d_in[5];   // [N, V]
    float* out = (float*)d_out;                 // [B, V]

    ctx_act_kernel<<<BATCH, 256>>>(tok, te, pe, q, pos);

    dim3 grid((VOCAB + VTILE - 1) / VTILE, BATCH);
    logits_kernel<<<grid, 256>>>(W, out);
}

// round 3
// speedup vs baseline: 1.3677x; 1.3653x over previous
#include <cuda_runtime.h>
#include <cstdint>

#define BATCH   4096
#define SEQ     32
#define DIM     256
#define VOCAB   50257
#define NALIVE  100

// Fused grid: 16384 blocks. Every 4th block (bid%4==0) is a ctx block (4096 of
// them); the other 12288 are zero-fill blocks. Interleaving keeps the DRAM
// write stream saturated from wave 1 while gathers overlap.
#define NBTOT   16384
#define NZB     12288
#define TOTAL4  51463168   // BATCH*VOCAB/4 (exact: 4096*50257 = 205,852,672)

// Scratch (no allocations allowed): compacted nonzero activations per row.
__device__ float g_val[BATCH * NALIVE];
__device__ int   g_idx[BATCH * NALIVE];
__device__ int   g_cnt[BATCH];

__device__ __forceinline__ float warp_sum(float v) {
    #pragma unroll
    for (int off = 16; off > 0; off >>= 1)
        v += __shfl_xor_sync(0xFFFFFFFFu, v, off);
    return v;
}
__device__ __forceinline__ float warp_max(float v) {
    #pragma unroll
    for (int off = 16; off > 0; off >>= 1)
        v = fmaxf(v, __shfl_xor_sync(0xFFFFFFFFu, v, off));
    return v;
}

__global__ __launch_bounds__(256)
void fused_fill_ctx_kernel(const int*   __restrict__ tok,
                           const float* __restrict__ te,
                           const float* __restrict__ pe,
                           const float* __restrict__ q,
                           const float* __restrict__ pos,
                           float*       __restrict__ out) {
    const int bid = blockIdx.x;
    const int tid = threadIdx.x;            // 0..255

    if ((bid & 3) != 0) {
        // ---------------- zero-fill role (12288 blocks) ----------------
        // zid = bid minus the number of ctx blocks below it.
        const int zid = bid - ((bid + 3) >> 2);          // 0..12287
        const float4 z = make_float4(0.f, 0.f, 0.f, 0.f);
        float4* __restrict__ o4 = (float4*)out;
        const long stride = (long)NZB * 256;
        for (long i = (long)zid * 256 + tid; i < (long)TOTAL4; i += stride)
            __stcs(o4 + i, z);
        return;
    }

    // ---------------- ctx role (4096 blocks, b = bid/4) ----------------
    const int b = bid >> 2;

    __shared__ float s_emb[SEQ][DIM];     // 32 KB
    __shared__ float s_q[DIM];
    __shared__ float s_ctx[DIM];
    __shared__ float s_score[SEQ];
    __shared__ float s_w[SEQ];
    __shared__ float s_act[NALIVE];
    __shared__ int   s_tok[SEQ];

    const int lane = tid & 31;
    const int wid  = tid >> 5;             // 0..7

    s_q[tid] = q[tid];
    if (tid < SEQ) s_tok[tid] = tok[b * SEQ + tid];
    __syncthreads();

    // Phase A: vectorized gather. 64 threads per row, 4 rows per pass, 8 passes.
    {
        const int rlane = tid & 63;        // float4 index within a row
        const int rgrp  = tid >> 6;        // 0..3
        #pragma unroll
        for (int p = 0; p < 8; p++) {
            const int s = p * 4 + rgrp;
            const float4 t4 = __ldg((const float4*)(te + (size_t)s_tok[s] * DIM) + rlane);
            const float4 p4 = __ldg((const float4*)(pe + s * DIM) + rlane);
            float4 e;
            e.x = t4.x + p4.x; e.y = t4.y + p4.y;
            e.z = t4.z + p4.z; e.w = t4.w + p4.w;
            *((float4*)&s_emb[s][0] + rlane) = e;
        }
    }
    __syncthreads();

    // Phase B: attention scores (warp w handles s = w, w+8, w+16, w+24)
    #pragma unroll
    for (int s = wid; s < SEQ; s += 8) {
        float p = 0.f;
        #pragma unroll
        for (int i = 0; i < 8; i++) {
            int d = lane + 32 * i;
            p = fmaf(s_emb[s][d], s_q[d], p);
        }
        p = warp_sum(p);
        if (lane == 0) s_score[s] = p * (1.0f / 16.0f);   // / sqrt(256)
    }
    __syncthreads();

    // Phase C: softmax over S=32 (warp 0, one score per lane)
    if (wid == 0) {
        float sc = s_score[lane];
        float m  = warp_max(sc);
        float e  = expf(sc - m);
        float s  = warp_sum(e);
        s_w[lane] = e / s;
    }
    __syncthreads();

    // Phase D: context[d] = sum_s w[s] * embeds[s][d]
    {
        float c = 0.f;
        #pragma unroll
        for (int s = 0; s < SEQ; s++) c = fmaf(s_w[s], s_emb[s][tid], c);
        s_ctx[tid] = c;
    }
    __syncthreads();

    // Phase E: RBF distances to 100 positions (warp w handles j = w, w+8, ...)
    for (int j = wid; j < NALIVE; j += 8) {
        float p = 0.f;
        #pragma unroll
        for (int i = 0; i < 8; i++) {
            int d = lane + 32 * i;
            float df = s_ctx[d] - pos[j * DIM + d];
            p = fmaf(df, df, p);
        }
        p = warp_sum(p);
        if (lane == 0) s_act[j] = expf(-2.0f * p);   // exp(-d2 / (2*0.5^2))
    }
    __syncthreads();

    // Phase F: normalize + compact nonzeros (warp 0)
    if (wid == 0) {
        float sum = 0.f;
        for (int j = lane; j < NALIVE; j += 32) sum += s_act[j];
        sum = warp_sum(sum);
        const float denom = sum + 1e-8f;

        int cnt = 0;
        #pragma unroll
        for (int base = 0; base < NALIVE; base += 32) {
            int j = base + lane;
            float a = 0.f;
            bool nz = false;
            if (j < NALIVE) {
                a  = s_act[j] / denom;
                nz = (a != 0.0f);
            }
            unsigned m = __ballot_sync(0xFFFFFFFFu, nz);
            int pre = __popc(m & ((1u << lane) - 1u));
            if (nz) {
                g_val[b * NALIVE + cnt + pre] = a;
                g_idx[b * NALIVE + cnt + pre] = j;
            }
            cnt += __popc(m);
        }
        if (lane == 0) g_cnt[b] = cnt;
    }
}

// Sparse fixup: rows whose activations did not all underflow get their logits
// recomputed (overwriting the zero-fill). In practice cnt==0 for every row,
// so this is 4096 early-exit blocks (~ a few microseconds).
__global__ __launch_bounds__(256)
void fixup_kernel(const float* __restrict__ W, float* __restrict__ out) {
    const int b   = blockIdx.x;
    const int cnt = g_cnt[b];
    if (cnt == 0) return;

    __shared__ float s_val[NALIVE];
    __shared__ int   s_idx[NALIVE];
    const int tid = threadIdx.x;
    if (tid < cnt) {
        s_val[tid] = g_val[b * NALIVE + tid];
        s_idx[tid] = g_idx[b * NALIVE + tid];
    }
    __syncthreads();

    float* __restrict__ orow = out + (size_t)b * VOCAB;
    for (int v = tid; v < VOCAB; v += 256) {
        float acc = 0.f;
        for (int k = 0; k < cnt; k++)
            acc = fmaf(s_val[k], W[(size_t)s_idx[k] * VOCAB + v], acc);
        orow[v] = acc;
    }
}

extern "C" void kernel_launch(void* const* d_in, const int* in_sizes, int n_in,
                              void* d_out, int out_size) {
    const int*   tok = (const int*)  d_in[0];   // [B, S]
    const float* te  = (const float*)d_in[1];   // [V, D]
    const float* pe  = (const float*)d_in[2];   // [S, D]
    const float* q   = (const float*)d_in[3];   // [D]
    const float* pos = (const float*)d_in[4];   // [N, D]
    const float* W   = (const float*)d_in[5];   // [N, V]
    float* out = (float*)d_out;                 // [B, V]

    fused_fill_ctx_kernel<<<NBTOT, 256>>>(tok, te, pe, q, pos, out);
    fixup_kernel<<<BATCH, 256>>>(W, out);
}